// round 15
// baseline (speedup 1.0000x reference)
#include <cuda_runtime.h>
#include <cuda_bf16.h>
#include <math.h>

#define MAXN 100000
#define MAXE 1600000
#define MAXEP (MAXE + 4 * MAXN)   // CSR padded to 4-aligned rows
#define NGRAPH 512

// ------------------------- device scratch ----------
// Dummy zero rows: padding col index = 2n (never-written regions; idempotent).
__device__ float g_A[(size_t)(MAXN + 1) * 128];
__device__ float g_B[(size_t)(MAXN + 1) * 128];
__device__ int   g_deg[MAXN];
__device__ int   g_tmp[MAXN];
__device__ int   g_rowptr[MAXN + 1];
__device__ int   g_cursor[MAXN];
__device__ int2  g_ecol[MAXEP];             // packed {col, edinv-bits} per CSR slot
__device__ float g_dinv[MAXN];
__device__ int   g_bsums[128];
__device__ float g_stats[1024];             // [0,64)=L1 [64,192)=L2 [192,448)=L3 [448,704)=L4
__device__ unsigned g_poolu[NGRAPH * 128];  // order-encoded float max
__device__ float g_q[NGRAPH * 128];

__device__ __forceinline__ unsigned enc_f(float f) {
    unsigned b = __float_as_uint(f);
    return (b & 0x80000000u) ? ~b : (b | 0x80000000u);
}
__device__ __forceinline__ float dec_f(unsigned k) {
    unsigned b = (k & 0x80000000u) ? (k ^ 0x80000000u) : ~k;
    return __uint_as_float(b);
}

// ------------------------------- setup kernels ------------------------------
__global__ void deg_kernel(const int* __restrict__ dst, int e) {
    int i = blockIdx.x * blockDim.x + threadIdx.x;
    if (i < e) atomicAdd(&g_deg[dst[i]], 1);
}

__global__ void scan_block_kernel(int n) {
    __shared__ int s[1024];
    int i = blockIdx.x * 1024 + threadIdx.x;
    int v = (i < n) ? ((g_deg[i] + 3) & ~3) : 0;
    s[threadIdx.x] = v;
    __syncthreads();
    for (int off = 1; off < 1024; off <<= 1) {
        int t = (threadIdx.x >= off) ? s[threadIdx.x - off] : 0;
        __syncthreads();
        s[threadIdx.x] += t;
        __syncthreads();
    }
    if (i < n) g_tmp[i] = s[threadIdx.x];
    if (threadIdx.x == 1023) g_bsums[blockIdx.x] = s[1023];
}

__global__ void scan_fin2_kernel(int n, int nb) {
    __shared__ int s[128];
    int tid = threadIdx.x;
    if (tid < 128) s[tid] = (tid < nb) ? g_bsums[tid] : 0;
    __syncthreads();
    for (int off = 1; off < 128; off <<= 1) {
        int t = 0;
        if (tid < 128 && tid >= off) t = s[tid - off];
        __syncthreads();
        if (tid < 128) s[tid] += t;
        __syncthreads();
    }
    int boff = (blockIdx.x == 0) ? 0 : s[blockIdx.x - 1];
    int i = blockIdx.x * 1024 + tid;
    if (i < 1024) g_stats[i] = 0.f;
    if (i < NGRAPH * 128) g_poolu[i] = 0u;
    if (i >= n) return;
    int incl = g_tmp[i] + boff;
    int deg = g_deg[i];
    int pdeg = (deg + 3) & ~3;
    g_rowptr[i + 1] = incl;
    g_cursor[i] = incl - pdeg;
    g_dinv[i] = rsqrtf((float)(deg + 1));
    for (int k = deg; k < pdeg; k++) {
        g_ecol[incl - pdeg + k] = make_int2(2 * n, 0);   // edinv bits 0 == 0.0f
    }
    g_deg[i] = 0;   // ready for next launch
    if (i == 0) g_rowptr[0] = 0;
}

// merged: first eblocks blocks do CSR fill (edge-parallel); remaining blocks do
// gemm1 (node-parallel). Both depend only on scan_fin2 -> run concurrently.
__global__ void fill_gemm1_kernel(const int* __restrict__ src, const int* __restrict__ dst,
                                  const float* __restrict__ x, const float* __restrict__ W,
                                  int n, int e, int eblocks) {
    __shared__ float Ws[6 * 32];
    int tid = threadIdx.x;
    if (blockIdx.x < eblocks) {
        int i = blockIdx.x * blockDim.x + tid;
        if (i < e) {
            int s = src[i];
            int p = atomicAdd(&g_cursor[dst[i]], 1);
            g_ecol[p] = make_int2(s, __float_as_int(g_dinv[s]));   // single 8B scatter
        }
    } else {
        if (tid < 6 * 32) Ws[tid] = W[tid];
        __syncthreads();
        int i = (blockIdx.x - eblocks) * blockDim.x + tid;
        if (i >= n) return;
        float xv[6];
#pragma unroll
        for (int k = 0; k < 6; k++) xv[k] = x[(size_t)i * 6 + k];
        float dv = g_dinv[i];
        size_t base = (size_t)i * 32;
#pragma unroll
        for (int c = 0; c < 32; c++) {
            float acc = 0.f;
#pragma unroll
            for (int k = 0; k < 6; k++) acc = fmaf(xv[k], Ws[k * 32 + c], acc);
            g_A[base + c] = dv * acc;
        }
    }
}

// agg32: o1 = dinv_d * sum hs + b1 ; stats1 ; write w1 = o1 * dinv_d -> g_B [N,32]
__global__ void agg32_kernel(const float* __restrict__ bias, int n) {
    __shared__ float sred[64];
    int tid = threadIdx.x;
    if (tid < 64) sred[tid] = 0.f;
    __syncthreads();
    int lane = tid & 31;
    int nw = (gridDim.x * blockDim.x) >> 5;
    int gw = (blockIdx.x * blockDim.x + tid) >> 5;
    float b = bias[lane];
    float ps = 0.f, pq = 0.f;
    for (int d = gw; d < n; d += nw) {
        float a1 = g_A[(size_t)d * 32 + lane];
        float a2 = 0.f, a3 = 0.f, a4 = 0.f;
        int beg = g_rowptr[d], end = g_rowptr[d + 1];
        for (int j = beg; j < end; j += 4) {
            int4 q0 = *(const int4*)&g_ecol[j];
            int4 q1 = *(const int4*)&g_ecol[j + 2];
            a1 += g_A[(size_t)q0.x * 32 + lane];
            a2 += g_A[(size_t)q0.z * 32 + lane];
            a3 += g_A[(size_t)q1.x * 32 + lane];
            a4 += g_A[(size_t)q1.z * 32 + lane];
        }
        float acc = (a1 + a2) + (a3 + a4);
        float dv = g_dinv[d];
        float o = fmaf(dv, acc, b);
        g_B[(size_t)d * 32 + lane] = o * dv;   // w1
        ps += o; pq += o * o;
    }
    atomicAdd(&sred[lane], ps);
    atomicAdd(&sred[32 + lane], pq);
    __syncthreads();
    if (tid < 64) atomicAdd(&g_stats[tid], sred[tid]);
}

// ------------------------------- layer 2 (fused, 4-node-blocked GEMM) --------
__global__ void layer2_kernel(const float* __restrict__ W, const float* __restrict__ bias,
                              const float* __restrict__ gamma, const float* __restrict__ beta,
                              float invn, int n) {
    __shared__ float Ws[32 * 64];
    __shared__ float ssc[32], ssh[32];
    __shared__ float sred[128];
    int tid = threadIdx.x;
    for (int i = tid; i < 32 * 64; i += blockDim.x) Ws[i] = W[i];
    if (tid < 32) {
        float m = g_stats[tid] * invn;
        float var = g_stats[32 + tid] * invn - m * m;
        float s = gamma[tid] * rsqrtf(var + 1e-5f);
        ssc[tid] = s;
        ssh[tid] = fmaf(-m, s, beta[tid]);
    }
    if (tid < 128) sred[tid] = 0.f;
    __syncthreads();
    int lane = tid & 31;
    int nwarp = (gridDim.x * blockDim.x) >> 5;
    int w = (blockIdx.x * blockDim.x + tid) >> 5;
    int chunk = (n + nwarp - 1) / nwarp;   // 8
    int beg_d = min(w * chunk, n);
    int end_d = min(beg_d + chunk, n);
    float sc = ssc[lane], sh = ssh[lane];
    float b0 = bias[lane], b1 = bias[32 + lane];
    float ps0 = 0.f, ps1 = 0.f, pq0 = 0.f, pq1 = 0.f;
    for (int d0 = beg_d; d0 < end_d; d0 += 4) {
        int cnt = min(4, end_d - d0);
        float u[4], dv[4];
#pragma unroll
        for (int m = 0; m < 4; m++) {
            u[m] = 0.f; dv[m] = 0.f;
            if (m < cnt) {
                int d = d0 + m;
                float dvd = g_dinv[d];
                dv[m] = dvd;
                float wv = g_B[(size_t)d * 32 + lane];
                float u1 = fmaxf(fmaf(sc, wv, sh * dvd), 0.f);
                float u2 = 0.f, u3 = 0.f, u4 = 0.f;
                int beg = g_rowptr[d], end = g_rowptr[d + 1];
                for (int j = beg; j < end; j += 4) {
                    int4 q0 = *(const int4*)&g_ecol[j];
                    int4 q1 = *(const int4*)&g_ecol[j + 2];
                    float v0 = g_B[(size_t)q0.x * 32 + lane];
                    float v1 = g_B[(size_t)q0.z * 32 + lane];
                    float v2 = g_B[(size_t)q1.x * 32 + lane];
                    float v3 = g_B[(size_t)q1.z * 32 + lane];
                    u1 += fmaxf(fmaf(sc, v0, sh * __int_as_float(q0.y)), 0.f);
                    u2 += fmaxf(fmaf(sc, v1, sh * __int_as_float(q0.w)), 0.f);
                    u3 += fmaxf(fmaf(sc, v2, sh * __int_as_float(q1.y)), 0.f);
                    u4 += fmaxf(fmaf(sc, v3, sh * __int_as_float(q1.w)), 0.f);
                }
                u[m] = (u1 + u2) + (u3 + u4);
            }
        }
        float ac0[4] = {0.f, 0.f, 0.f, 0.f};
        float ac1[4] = {0.f, 0.f, 0.f, 0.f};
#pragma unroll
        for (int k = 0; k < 32; k++) {
            float w0 = Ws[k * 64 + lane];
            float w1v = Ws[k * 64 + 32 + lane];
#pragma unroll
            for (int m = 0; m < 4; m++) {
                float v = __shfl_sync(0xffffffffu, u[m], k);
                ac0[m] = fmaf(v, w0, ac0[m]);
                ac1[m] = fmaf(v, w1v, ac1[m]);
            }
        }
#pragma unroll
        for (int m = 0; m < 4; m++) {
            if (m < cnt) {
                float o0 = fmaf(ac0[m], dv[m], b0);
                float o1 = fmaf(ac1[m], dv[m], b1);
                size_t ob = (size_t)(d0 + m) * 64;
                g_A[ob + lane] = o0 * dv[m];       // w2
                g_A[ob + 32 + lane] = o1 * dv[m];
                ps0 += o0; ps1 += o1; pq0 += o0 * o0; pq1 += o1 * o1;
            }
        }
    }
    atomicAdd(&sred[lane], ps0);
    atomicAdd(&sred[32 + lane], ps1);
    atomicAdd(&sred[64 + lane], pq0);
    atomicAdd(&sred[96 + lane], pq1);
    __syncthreads();
    if (tid < 128) atomicAdd(&g_stats[64 + tid], sred[tid]);
}

// ------------------------------- layer 3 (fused, 4-node-blocked GEMM+pool) ---
__global__ void layer3_kernel(const float* __restrict__ W, const float* __restrict__ bias,
                              const float* __restrict__ gamma, const float* __restrict__ beta,
                              const int* __restrict__ batch, float invn, int n) {
    __shared__ float Ws[64 * 128];   // 32 KB
    __shared__ float ssc[64], ssh[64];
    __shared__ float sred[256];
    int tid = threadIdx.x;
    for (int i = tid; i < 64 * 128; i += blockDim.x) Ws[i] = W[i];
    if (tid < 64) {
        float m = g_stats[64 + tid] * invn;
        float var = g_stats[128 + tid] * invn - m * m;
        float s = gamma[tid] * rsqrtf(var + 1e-5f);
        ssc[tid] = s;
        ssh[tid] = fmaf(-m, s, beta[tid]);
    }
    if (tid < 256) sred[tid] = 0.f;
    __syncthreads();
    int lane = tid & 31;
    int nwarp = (gridDim.x * blockDim.x) >> 5;
    int w = (blockIdx.x * blockDim.x + tid) >> 5;
    int chunk = (n + nwarp - 1) / nwarp;
    int beg_d = min(w * chunk, n);
    int end_d = min(beg_d + chunk, n);
    int c0 = lane * 2;
    float sc0 = ssc[c0], sc1 = ssc[c0 + 1];
    float sh0 = ssh[c0], sh1 = ssh[c0 + 1];
    float bb0 = bias[lane], bb1 = bias[32 + lane];
    float bb2 = bias[64 + lane], bb3 = bias[96 + lane];
    float ps[4] = {0.f, 0.f, 0.f, 0.f};
    float pq[4] = {0.f, 0.f, 0.f, 0.f};
    float m0 = -INFINITY, m1 = -INFINITY, m2 = -INFINITY, m3 = -INFINITY;
    int cur = -1;
    for (int d0 = beg_d; d0 < end_d; d0 += 4) {
        int cnt = min(4, end_d - d0);
        float ux[4], uy[4], dv[4];
#pragma unroll
        for (int m = 0; m < 4; m++) {
            ux[m] = 0.f; uy[m] = 0.f; dv[m] = 0.f;
            if (m < cnt) {
                int d = d0 + m;
                float dvd = g_dinv[d];
                dv[m] = dvd;
                float2 wf = *(const float2*)&g_A[(size_t)d * 64 + c0];
                float ax1 = fmaxf(fmaf(sc0, wf.x, sh0 * dvd), 0.f);
                float ay1 = fmaxf(fmaf(sc1, wf.y, sh1 * dvd), 0.f);
                float ax2 = 0.f, ay2 = 0.f, ax3 = 0.f, ay3 = 0.f, ax4 = 0.f, ay4 = 0.f;
                int jb = g_rowptr[d], je = g_rowptr[d + 1];
                for (int j = jb; j < je; j += 4) {
                    int4 q0 = *(const int4*)&g_ecol[j];
                    int4 q1 = *(const int4*)&g_ecol[j + 2];
                    float e0 = __int_as_float(q0.y), e1 = __int_as_float(q0.w);
                    float e2 = __int_as_float(q1.y), e3 = __int_as_float(q1.w);
                    float2 v0 = *(const float2*)&g_A[(size_t)q0.x * 64 + c0];
                    float2 v1 = *(const float2*)&g_A[(size_t)q0.z * 64 + c0];
                    float2 v2 = *(const float2*)&g_A[(size_t)q1.x * 64 + c0];
                    float2 v3 = *(const float2*)&g_A[(size_t)q1.z * 64 + c0];
                    ax1 += fmaxf(fmaf(sc0, v0.x, sh0 * e0), 0.f);
                    ay1 += fmaxf(fmaf(sc1, v0.y, sh1 * e0), 0.f);
                    ax2 += fmaxf(fmaf(sc0, v1.x, sh0 * e1), 0.f);
                    ay2 += fmaxf(fmaf(sc1, v1.y, sh1 * e1), 0.f);
                    ax3 += fmaxf(fmaf(sc0, v2.x, sh0 * e2), 0.f);
                    ay3 += fmaxf(fmaf(sc1, v2.y, sh1 * e2), 0.f);
                    ax4 += fmaxf(fmaf(sc0, v3.x, sh0 * e3), 0.f);
                    ay4 += fmaxf(fmaf(sc1, v3.y, sh1 * e3), 0.f);
                }
                ux[m] = (ax1 + ax2) + (ax3 + ax4);
                uy[m] = (ay1 + ay2) + (ay3 + ay4);
            }
        }
        float ac0[4] = {0.f, 0.f, 0.f, 0.f};
        float ac1[4] = {0.f, 0.f, 0.f, 0.f};
        float ac2[4] = {0.f, 0.f, 0.f, 0.f};
        float ac3[4] = {0.f, 0.f, 0.f, 0.f};
#pragma unroll
        for (int kk = 0; kk < 32; kk++) {
            const float* w0 = &Ws[(2 * kk) * 128];
            const float* w1 = &Ws[(2 * kk + 1) * 128];
            float w00 = w0[lane],      w10 = w1[lane];
            float w01 = w0[32 + lane], w11 = w1[32 + lane];
            float w02 = w0[64 + lane], w12 = w1[64 + lane];
            float w03 = w0[96 + lane], w13 = w1[96 + lane];
#pragma unroll
            for (int m = 0; m < 4; m++) {
                float vx = __shfl_sync(0xffffffffu, ux[m], kk);
                float vy = __shfl_sync(0xffffffffu, uy[m], kk);
                ac0[m] = fmaf(vx, w00, ac0[m]); ac0[m] = fmaf(vy, w10, ac0[m]);
                ac1[m] = fmaf(vx, w01, ac1[m]); ac1[m] = fmaf(vy, w11, ac1[m]);
                ac2[m] = fmaf(vx, w02, ac2[m]); ac2[m] = fmaf(vy, w12, ac2[m]);
                ac3[m] = fmaf(vx, w03, ac3[m]); ac3[m] = fmaf(vy, w13, ac3[m]);
            }
        }
#pragma unroll
        for (int m = 0; m < 4; m++) {
            if (m < cnt) {
                int d = d0 + m;
                int bg = batch[d];
                if (bg != cur) {
                    if (cur >= 0) {
                        atomicMax(&g_poolu[cur * 128 + lane],      enc_f(m0));
                        atomicMax(&g_poolu[cur * 128 + 32 + lane], enc_f(m1));
                        atomicMax(&g_poolu[cur * 128 + 64 + lane], enc_f(m2));
                        atomicMax(&g_poolu[cur * 128 + 96 + lane], enc_f(m3));
                    }
                    cur = bg;
                    m0 = m1 = m2 = m3 = -INFINITY;
                }
                float o0 = fmaf(ac0[m], dv[m], bb0);
                float o1 = fmaf(ac1[m], dv[m], bb1);
                float o2 = fmaf(ac2[m], dv[m], bb2);
                float o3 = fmaf(ac3[m], dv[m], bb3);
                ps[0] += o0; ps[1] += o1; ps[2] += o2; ps[3] += o3;
                pq[0] += o0 * o0; pq[1] += o1 * o1; pq[2] += o2 * o2; pq[3] += o3 * o3;
                m0 = fmaxf(m0, o0); m1 = fmaxf(m1, o1);
                m2 = fmaxf(m2, o2); m3 = fmaxf(m3, o3);
            }
        }
    }
    if (cur >= 0) {
        atomicMax(&g_poolu[cur * 128 + lane],      enc_f(m0));
        atomicMax(&g_poolu[cur * 128 + 32 + lane], enc_f(m1));
        atomicMax(&g_poolu[cur * 128 + 64 + lane], enc_f(m2));
        atomicMax(&g_poolu[cur * 128 + 96 + lane], enc_f(m3));
    }
    atomicAdd(&sred[lane], ps[0]);
    atomicAdd(&sred[32 + lane], ps[1]);
    atomicAdd(&sred[64 + lane], ps[2]);
    atomicAdd(&sred[96 + lane], ps[3]);
    atomicAdd(&sred[128 + lane], pq[0]);
    atomicAdd(&sred[160 + lane], pq[1]);
    atomicAdd(&sred[192 + lane], pq[2]);
    atomicAdd(&sred[224 + lane], pq[3]);
    __syncthreads();
    if (tid < 256) atomicAdd(&g_stats[192 + tid], sred[tid]);
}

// --------------------------------- final MLP ----------------------------------
__global__ void fc1_kernel(const float* __restrict__ Wf1, const float* __restrict__ bf1,
                           const float* __restrict__ g3, const float* __restrict__ be3,
                           float invn) {
    __shared__ float pr[128];
    int g = blockIdx.x, t = threadIdx.x;
    {
        float mm = g_stats[192 + t] * invn;
        float var = g_stats[320 + t] * invn - mm * mm;
        float s = g3[t] * rsqrtf(var + 1e-5f);
        float sh = fmaf(-mm, s, be3[t]);
        float raw = dec_f(g_poolu[g * 128 + t]);
        pr[t] = fmaxf(fmaf(s, raw, sh), 0.f);
    }
    __syncthreads();
    float acc = bf1[t];
#pragma unroll 8
    for (int k = 0; k < 128; k++) acc = fmaf(pr[k], Wf1[k * 128 + t], acc);
    g_q[g * 128 + t] = acc;
    atomicAdd(&g_stats[448 + t], acc);
    atomicAdd(&g_stats[576 + t], acc * acc);
}

__global__ void fc2_kernel(const float* __restrict__ Wf2, const float* __restrict__ bf2,
                           const float* __restrict__ g4, const float* __restrict__ be4,
                           float* __restrict__ out) {
    __shared__ float r[128];
    __shared__ float red[64];
    int g = blockIdx.x, t = threadIdx.x;  // 64 threads
    const float invg = 1.0f / (float)NGRAPH;
#pragma unroll
    for (int h = 0; h < 2; h++) {
        int c = t + 64 * h;
        float mm = g_stats[448 + c] * invg;
        float var = g_stats[576 + c] * invg - mm * mm;
        float s = g4[c] * rsqrtf(var + 1e-5f);
        float sh = fmaf(-mm, s, be4[c]);
        r[c] = fmaxf(fmaf(s, g_q[g * 128 + c], sh), 0.f);
    }
    __syncthreads();
    float acc = bf2[t];
#pragma unroll 8
    for (int k = 0; k < 128; k++) acc = fmaf(r[k], Wf2[k * 64 + t], acc);
    red[t] = acc * acc;
    for (int off = 32; off > 0; off >>= 1) {
        __syncthreads();
        if (t < off) red[t] += red[t + off];
    }
    __syncthreads();
    float denom = fmaxf(sqrtf(red[0]), 1e-12f);
    out[g * 64 + t] = acc / denom;
}

// --------------------------------- launcher -----------------------------------
extern "C" void kernel_launch(void* const* d_in, const int* in_sizes, int n_in,
                              void* d_out, int out_size) {
    const float* x    = (const float*)d_in[0];
    const int* src    = (const int*)d_in[1];
    const int* dst    = (const int*)d_in[2];
    const int* batch  = (const int*)d_in[3];
    const float* W1  = (const float*)d_in[4];
    const float* b1  = (const float*)d_in[5];
    const float* G1  = (const float*)d_in[6];
    const float* be1 = (const float*)d_in[7];
    const float* W2  = (const float*)d_in[8];
    const float* b2  = (const float*)d_in[9];
    const float* G2  = (const float*)d_in[10];
    const float* be2 = (const float*)d_in[11];
    const float* W3  = (const float*)d_in[12];
    const float* b3  = (const float*)d_in[13];
    const float* G3  = (const float*)d_in[14];
    const float* be3 = (const float*)d_in[15];
    const float* Wf1 = (const float*)d_in[16];
    const float* bf1 = (const float*)d_in[17];
    const float* G4  = (const float*)d_in[18];
    const float* be4 = (const float*)d_in[19];
    const float* Wf2 = (const float*)d_in[20];
    const float* bf2 = (const float*)d_in[21];

    int n = in_sizes[0] / 6;
    int e = in_sizes[1];
    int nb = (n + 1023) / 1024;
    float invn = 1.0f / (float)n;

    deg_kernel<<<(e + 255) / 256, 256>>>(dst, e);
    scan_block_kernel<<<nb, 1024>>>(n);
    scan_fin2_kernel<<<nb, 1024>>>(n, nb);

    // fill + gemm1 merged (independent work, same dependency set)
    int eblocks = (e + 255) / 256;
    int nblocks = (n + 255) / 256;
    fill_gemm1_kernel<<<eblocks + nblocks, 256>>>(src, dst, x, W1, n, e, eblocks);

    int l23blocks = (n + 63) / 64;   // 8-node chunks per warp (two 4-groups)

    agg32_kernel<<<2048, 256>>>(b1, n);
    layer2_kernel<<<l23blocks, 256>>>(W2, b2, G1, be1, invn, n);
    layer3_kernel<<<l23blocks, 256>>>(W3, b3, G2, be2, batch, invn, n);
    fc1_kernel<<<NGRAPH, 128>>>(Wf1, bf1, G3, be3, invn);
    fc2_kernel<<<NGRAPH, 64>>>(Wf2, bf2, G4, be4, (float*)d_out);
}

// round 16
// speedup vs baseline: 1.0743x; 1.0743x over previous
#include <cuda_runtime.h>
#include <cuda_bf16.h>
#include <math.h>

#define MAXN 100000
#define MAXE 1600000
#define MAXEP (MAXE + 4 * MAXN)   // CSR padded to 4-aligned rows
#define NGRAPH 512

// ------------------------- device scratch ----------
// Dummy zero rows: padding col index = 2n (never-written regions; idempotent).
__device__ float g_A[(size_t)(MAXN + 1) * 128];   // layer2 out (w2) [N,64]; dummy reads at 128n
__device__ float g_B[(size_t)(MAXN + 1) * 128];   // layer1 out (o1) [N,32]; dummy reads at 64n
__device__ float g_Y[(size_t)(2 * MAXN + 2) * 8]; // y = dinv*x padded [N,8]; dummy at 16n
__device__ int   g_deg[MAXN];
__device__ int   g_tmp[MAXN];
__device__ int   g_rowptr[MAXN + 1];
__device__ int   g_cursor[MAXN];
__device__ int2  g_ecol[MAXEP];             // packed {col, edinv-bits} per CSR slot
__device__ float g_dinv[MAXN];
__device__ int   g_bsums[128];
__device__ float g_stats[1024];             // [0,64)=L1 [64,192)=L2 [192,448)=L3 [448,704)=L4
__device__ unsigned g_poolu[NGRAPH * 128];  // order-encoded float max
__device__ float g_q[NGRAPH * 128];

__device__ __forceinline__ unsigned enc_f(float f) {
    unsigned b = __float_as_uint(f);
    return (b & 0x80000000u) ? ~b : (b | 0x80000000u);
}
__device__ __forceinline__ float dec_f(unsigned k) {
    unsigned b = (k & 0x80000000u) ? (k ^ 0x80000000u) : ~k;
    return __uint_as_float(b);
}

// ------------------------------- setup kernels ------------------------------
__global__ void deg_kernel(const int* __restrict__ dst, int e) {
    int i = blockIdx.x * blockDim.x + threadIdx.x;
    if (i < e) atomicAdd(&g_deg[dst[i]], 1);
}

__global__ void scan_block_kernel(int n) {
    __shared__ int s[1024];
    int i = blockIdx.x * 1024 + threadIdx.x;
    int v = (i < n) ? ((g_deg[i] + 3) & ~3) : 0;
    s[threadIdx.x] = v;
    __syncthreads();
    for (int off = 1; off < 1024; off <<= 1) {
        int t = (threadIdx.x >= off) ? s[threadIdx.x - off] : 0;
        __syncthreads();
        s[threadIdx.x] += t;
        __syncthreads();
    }
    if (i < n) g_tmp[i] = s[threadIdx.x];
    if (threadIdx.x == 1023) g_bsums[blockIdx.x] = s[1023];
}

__global__ void scan_fin2_kernel(int n, int nb) {
    __shared__ int s[128];
    int tid = threadIdx.x;
    if (tid < 128) s[tid] = (tid < nb) ? g_bsums[tid] : 0;
    __syncthreads();
    for (int off = 1; off < 128; off <<= 1) {
        int t = 0;
        if (tid < 128 && tid >= off) t = s[tid - off];
        __syncthreads();
        if (tid < 128) s[tid] += t;
        __syncthreads();
    }
    int boff = (blockIdx.x == 0) ? 0 : s[blockIdx.x - 1];
    int i = blockIdx.x * 1024 + tid;
    if (i < 1024) g_stats[i] = 0.f;
    if (i < NGRAPH * 128) g_poolu[i] = 0u;
    if (i >= n) return;
    int incl = g_tmp[i] + boff;
    int deg = g_deg[i];
    int pdeg = (deg + 3) & ~3;
    g_rowptr[i + 1] = incl;
    g_cursor[i] = incl - pdeg;
    g_dinv[i] = rsqrtf((float)(deg + 1));
    for (int k = deg; k < pdeg; k++) {
        g_ecol[incl - pdeg + k] = make_int2(2 * n, 0);   // edinv bits 0 == 0.0f
    }
    g_deg[i] = 0;   // ready for next launch
    if (i == 0) g_rowptr[0] = 0;
}

__global__ void fill_kernel(const int* __restrict__ src, const int* __restrict__ dst, int e) {
    int i = blockIdx.x * blockDim.x + threadIdx.x;
    if (i < e) {
        int s = src[i];
        int p = atomicAdd(&g_cursor[dst[i]], 1);
        g_ecol[p] = make_int2(s, __float_as_int(g_dinv[s]));   // single 8B scatter
    }
}

// y = dinv * x, padded to 8 floats/row (32B = one sector)
__global__ void y_kernel(const float* __restrict__ x, int n) {
    int i = blockIdx.x * blockDim.x + threadIdx.x;
    if (i >= n) return;
    float dv = g_dinv[i];
    const float* xr = x + (size_t)i * 6;
    float* yr = &g_Y[(size_t)i * 8];
    *(float4*)yr = make_float4(xr[0] * dv, xr[1] * dv, xr[2] * dv, xr[3] * dv);
    *(float2*)(yr + 4) = make_float2(xr[4] * dv, xr[5] * dv);
}

// ------------------------------- layer 1 (swapped: 6-wide gather + GEMM) -----
// lane-per-node: u = sum_{N+(d)} y[s]  (1 sector/edge); o1 = (u@W1)*dinv_d + b1
// -> g_B [N,32] (raw o1); stats1 via warp butterflies.
__global__ void layer1_kernel(const float* __restrict__ W, const float* __restrict__ bias, int n) {
    __shared__ float Ws[6 * 32];
    __shared__ float sb[32];
    __shared__ float sred[64];
    int tid = threadIdx.x;
    for (int i = tid; i < 192; i += blockDim.x) Ws[i] = W[i];
    if (tid < 32) sb[tid] = bias[tid];
    if (tid < 64) sred[tid] = 0.f;
    __syncthreads();
    int lane = tid & 31;
    int nwarp = (gridDim.x * blockDim.x) >> 5;
    int w = (blockIdx.x * blockDim.x + tid) >> 5;
    int ngroups = (n + 31) >> 5;
    for (int grp = w; grp < ngroups; grp += nwarp) {
        int d = grp * 32 + lane;
        bool act = d < n;
        float u0 = 0.f, u1 = 0.f, u2 = 0.f, u3 = 0.f, u4 = 0.f, u5 = 0.f;
        float v0 = 0.f, v1 = 0.f, v2 = 0.f, v3 = 0.f, v4 = 0.f, v5 = 0.f;
        float dvd = 0.f;
        if (act) {
            dvd = g_dinv[d];
            const float* yr = &g_Y[(size_t)d * 8];
            float4 a = *(const float4*)yr;
            float2 b2 = *(const float2*)(yr + 4);
            u0 = a.x; u1 = a.y; u2 = a.z; u3 = a.w; u4 = b2.x; u5 = b2.y;
            int jb = g_rowptr[d], je = g_rowptr[d + 1];
            for (int j = jb; j < je; j += 2) {
                int4 q = *(const int4*)&g_ecol[j];   // 2 packed edges (16B aligned)
                const float* y0 = &g_Y[(size_t)q.x * 8];
                const float* y1 = &g_Y[(size_t)q.z * 8];
                float4 p0 = *(const float4*)y0; float2 r0 = *(const float2*)(y0 + 4);
                float4 p1 = *(const float4*)y1; float2 r1 = *(const float2*)(y1 + 4);
                u0 += p0.x; u1 += p0.y; u2 += p0.z; u3 += p0.w; u4 += r0.x; u5 += r0.y;
                v0 += p1.x; v1 += p1.y; v2 += p1.z; v3 += p1.w; v4 += r1.x; v5 += r1.y;
            }
            u0 += v0; u1 += v1; u2 += v2; u3 += v3; u4 += v4; u5 += v5;
        }
        // 6x32 GEMM per lane (broadcast weights), stats, row store
#pragma unroll
        for (int c = 0; c < 32; c += 4) {
            float o[4];
#pragma unroll
            for (int t = 0; t < 4; t++) {
                float acc = u0 * Ws[0 * 32 + c + t];
                acc = fmaf(u1, Ws[1 * 32 + c + t], acc);
                acc = fmaf(u2, Ws[2 * 32 + c + t], acc);
                acc = fmaf(u3, Ws[3 * 32 + c + t], acc);
                acc = fmaf(u4, Ws[4 * 32 + c + t], acc);
                acc = fmaf(u5, Ws[5 * 32 + c + t], acc);
                o[t] = act ? fmaf(acc, dvd, sb[c + t]) : 0.f;
            }
            if (act)
                *(float4*)&g_B[(size_t)d * 32 + c] = make_float4(o[0], o[1], o[2], o[3]);
#pragma unroll
            for (int t = 0; t < 4; t++) {
                float s1v = o[t], s2v = o[t] * o[t];
#pragma unroll
                for (int off = 16; off > 0; off >>= 1) {
                    s1v += __shfl_xor_sync(0xffffffffu, s1v, off);
                    s2v += __shfl_xor_sync(0xffffffffu, s2v, off);
                }
                if (lane == 0) {
                    atomicAdd(&sred[c + t], s1v);
                    atomicAdd(&sred[32 + c + t], s2v);
                }
            }
        }
    }
    __syncthreads();
    if (tid < 64) atomicAdd(&g_stats[tid], sred[tid]);
}

// ------------------------------- layer 2 (fused, 4-node-blocked GEMM) --------
// g_B holds raw o1: gather term = relu((sc*o + sh) * dinv_s)
__global__ void layer2_kernel(const float* __restrict__ W, const float* __restrict__ bias,
                              const float* __restrict__ gamma, const float* __restrict__ beta,
                              float invn, int n) {
    __shared__ float Ws[32 * 64];
    __shared__ float ssc[32], ssh[32];
    __shared__ float sred[128];
    int tid = threadIdx.x;
    for (int i = tid; i < 32 * 64; i += blockDim.x) Ws[i] = W[i];
    if (tid < 32) {
        float m = g_stats[tid] * invn;
        float var = g_stats[32 + tid] * invn - m * m;
        float s = gamma[tid] * rsqrtf(var + 1e-5f);
        ssc[tid] = s;
        ssh[tid] = fmaf(-m, s, beta[tid]);
    }
    if (tid < 128) sred[tid] = 0.f;
    __syncthreads();
    int lane = tid & 31;
    int nwarp = (gridDim.x * blockDim.x) >> 5;
    int w = (blockIdx.x * blockDim.x + tid) >> 5;
    int chunk = (n + nwarp - 1) / nwarp;   // 8
    int beg_d = min(w * chunk, n);
    int end_d = min(beg_d + chunk, n);
    float sc = ssc[lane], sh = ssh[lane];
    float b0 = bias[lane], b1 = bias[32 + lane];
    float ps0 = 0.f, ps1 = 0.f, pq0 = 0.f, pq1 = 0.f;
    for (int d0 = beg_d; d0 < end_d; d0 += 4) {
        int cnt = min(4, end_d - d0);
        float u[4], dv[4];
#pragma unroll
        for (int m = 0; m < 4; m++) {
            u[m] = 0.f; dv[m] = 0.f;
            if (m < cnt) {
                int d = d0 + m;
                float dvd = g_dinv[d];
                dv[m] = dvd;
                float wv = g_B[(size_t)d * 32 + lane];
                float u1 = fmaxf(fmaf(sc, wv, sh) * dvd, 0.f);     // self term
                float u2 = 0.f, u3 = 0.f, u4 = 0.f;
                int beg = g_rowptr[d], end = g_rowptr[d + 1];
                for (int j = beg; j < end; j += 4) {
                    int4 q0 = *(const int4*)&g_ecol[j];
                    int4 q1 = *(const int4*)&g_ecol[j + 2];
                    float v0 = g_B[(size_t)q0.x * 32 + lane];
                    float v1 = g_B[(size_t)q0.z * 32 + lane];
                    float v2 = g_B[(size_t)q1.x * 32 + lane];
                    float v3 = g_B[(size_t)q1.z * 32 + lane];
                    u1 += fmaxf(fmaf(sc, v0, sh) * __int_as_float(q0.y), 0.f);
                    u2 += fmaxf(fmaf(sc, v1, sh) * __int_as_float(q0.w), 0.f);
                    u3 += fmaxf(fmaf(sc, v2, sh) * __int_as_float(q1.y), 0.f);
                    u4 += fmaxf(fmaf(sc, v3, sh) * __int_as_float(q1.w), 0.f);
                }
                u[m] = (u1 + u2) + (u3 + u4);
            }
        }
        float ac0[4] = {0.f, 0.f, 0.f, 0.f};
        float ac1[4] = {0.f, 0.f, 0.f, 0.f};
#pragma unroll
        for (int k = 0; k < 32; k++) {
            float w0 = Ws[k * 64 + lane];
            float w1v = Ws[k * 64 + 32 + lane];
#pragma unroll
            for (int m = 0; m < 4; m++) {
                float v = __shfl_sync(0xffffffffu, u[m], k);
                ac0[m] = fmaf(v, w0, ac0[m]);
                ac1[m] = fmaf(v, w1v, ac1[m]);
            }
        }
#pragma unroll
        for (int m = 0; m < 4; m++) {
            if (m < cnt) {
                float o0 = fmaf(ac0[m], dv[m], b0);
                float o1 = fmaf(ac1[m], dv[m], b1);
                size_t ob = (size_t)(d0 + m) * 64;
                g_A[ob + lane] = o0 * dv[m];       // w2 (premultiplied)
                g_A[ob + 32 + lane] = o1 * dv[m];
                ps0 += o0; ps1 += o1; pq0 += o0 * o0; pq1 += o1 * o1;
            }
        }
    }
    atomicAdd(&sred[lane], ps0);
    atomicAdd(&sred[32 + lane], ps1);
    atomicAdd(&sred[64 + lane], pq0);
    atomicAdd(&sred[96 + lane], pq1);
    __syncthreads();
    if (tid < 128) atomicAdd(&g_stats[64 + tid], sred[tid]);
}

// ------------------------------- layer 3 (fused, 4-node-blocked GEMM+pool) ---
__global__ void layer3_kernel(const float* __restrict__ W, const float* __restrict__ bias,
                              const float* __restrict__ gamma, const float* __restrict__ beta,
                              const int* __restrict__ batch, float invn, int n) {
    __shared__ float Ws[64 * 128];   // 32 KB
    __shared__ float ssc[64], ssh[64];
    __shared__ float sred[256];
    int tid = threadIdx.x;
    for (int i = tid; i < 64 * 128; i += blockDim.x) Ws[i] = W[i];
    if (tid < 64) {
        float m = g_stats[64 + tid] * invn;
        float var = g_stats[128 + tid] * invn - m * m;
        float s = gamma[tid] * rsqrtf(var + 1e-5f);
        ssc[tid] = s;
        ssh[tid] = fmaf(-m, s, beta[tid]);
    }
    if (tid < 256) sred[tid] = 0.f;
    __syncthreads();
    int lane = tid & 31;
    int nwarp = (gridDim.x * blockDim.x) >> 5;
    int w = (blockIdx.x * blockDim.x + tid) >> 5;
    int chunk = (n + nwarp - 1) / nwarp;
    int beg_d = min(w * chunk, n);
    int end_d = min(beg_d + chunk, n);
    int c0 = lane * 2;
    float sc0 = ssc[c0], sc1 = ssc[c0 + 1];
    float sh0 = ssh[c0], sh1 = ssh[c0 + 1];
    float bb0 = bias[lane], bb1 = bias[32 + lane];
    float bb2 = bias[64 + lane], bb3 = bias[96 + lane];
    float ps[4] = {0.f, 0.f, 0.f, 0.f};
    float pq[4] = {0.f, 0.f, 0.f, 0.f};
    float m0 = -INFINITY, m1 = -INFINITY, m2 = -INFINITY, m3 = -INFINITY;
    int cur = -1;
    for (int d0 = beg_d; d0 < end_d; d0 += 4) {
        int cnt = min(4, end_d - d0);
        float ux[4], uy[4], dv[4];
#pragma unroll
        for (int m = 0; m < 4; m++) {
            ux[m] = 0.f; uy[m] = 0.f; dv[m] = 0.f;
            if (m < cnt) {
                int d = d0 + m;
                float dvd = g_dinv[d];
                dv[m] = dvd;
                float2 wf = *(const float2*)&g_A[(size_t)d * 64 + c0];
                float ax1 = fmaxf(fmaf(sc0, wf.x, sh0 * dvd), 0.f);
                float ay1 = fmaxf(fmaf(sc1, wf.y, sh1 * dvd), 0.f);
                float ax2 = 0.f, ay2 = 0.f, ax3 = 0.f, ay3 = 0.f, ax4 = 0.f, ay4 = 0.f;
                int jb = g_rowptr[d], je = g_rowptr[d + 1];
                for (int j = jb; j < je; j += 4) {
                    int4 q0 = *(const int4*)&g_ecol[j];
                    int4 q1 = *(const int4*)&g_ecol[j + 2];
                    float e0 = __int_as_float(q0.y), e1 = __int_as_float(q0.w);
                    float e2 = __int_as_float(q1.y), e3 = __int_as_float(q1.w);
                    float2 v0 = *(const float2*)&g_A[(size_t)q0.x * 64 + c0];
                    float2 v1 = *(const float2*)&g_A[(size_t)q0.z * 64 + c0];
                    float2 v2 = *(const float2*)&g_A[(size_t)q1.x * 64 + c0];
                    float2 v3 = *(const float2*)&g_A[(size_t)q1.z * 64 + c0];
                    ax1 += fmaxf(fmaf(sc0, v0.x, sh0 * e0), 0.f);
                    ay1 += fmaxf(fmaf(sc1, v0.y, sh1 * e0), 0.f);
                    ax2 += fmaxf(fmaf(sc0, v1.x, sh0 * e1), 0.f);
                    ay2 += fmaxf(fmaf(sc1, v1.y, sh1 * e1), 0.f);
                    ax3 += fmaxf(fmaf(sc0, v2.x, sh0 * e2), 0.f);
                    ay3 += fmaxf(fmaf(sc1, v2.y, sh1 * e2), 0.f);
                    ax4 += fmaxf(fmaf(sc0, v3.x, sh0 * e3), 0.f);
                    ay4 += fmaxf(fmaf(sc1, v3.y, sh1 * e3), 0.f);
                }
                ux[m] = (ax1 + ax2) + (ax3 + ax4);
                uy[m] = (ay1 + ay2) + (ay3 + ay4);
            }
        }
        float ac0[4] = {0.f, 0.f, 0.f, 0.f};
        float ac1[4] = {0.f, 0.f, 0.f, 0.f};
        float ac2[4] = {0.f, 0.f, 0.f, 0.f};
        float ac3[4] = {0.f, 0.f, 0.f, 0.f};
#pragma unroll
        for (int kk = 0; kk < 32; kk++) {
            const float* w0 = &Ws[(2 * kk) * 128];
            const float* w1 = &Ws[(2 * kk + 1) * 128];
            float w00 = w0[lane],      w10 = w1[lane];
            float w01 = w0[32 + lane], w11 = w1[32 + lane];
            float w02 = w0[64 + lane], w12 = w1[64 + lane];
            float w03 = w0[96 + lane], w13 = w1[96 + lane];
#pragma unroll
            for (int m = 0; m < 4; m++) {
                float vx = __shfl_sync(0xffffffffu, ux[m], kk);
                float vy = __shfl_sync(0xffffffffu, uy[m], kk);
                ac0[m] = fmaf(vx, w00, ac0[m]); ac0[m] = fmaf(vy, w10, ac0[m]);
                ac1[m] = fmaf(vx, w01, ac1[m]); ac1[m] = fmaf(vy, w11, ac1[m]);
                ac2[m] = fmaf(vx, w02, ac2[m]); ac2[m] = fmaf(vy, w12, ac2[m]);
                ac3[m] = fmaf(vx, w03, ac3[m]); ac3[m] = fmaf(vy, w13, ac3[m]);
            }
        }
#pragma unroll
        for (int m = 0; m < 4; m++) {
            if (m < cnt) {
                int d = d0 + m;
                int bg = batch[d];
                if (bg != cur) {
                    if (cur >= 0) {
                        atomicMax(&g_poolu[cur * 128 + lane],      enc_f(m0));
                        atomicMax(&g_poolu[cur * 128 + 32 + lane], enc_f(m1));
                        atomicMax(&g_poolu[cur * 128 + 64 + lane], enc_f(m2));
                        atomicMax(&g_poolu[cur * 128 + 96 + lane], enc_f(m3));
                    }
                    cur = bg;
                    m0 = m1 = m2 = m3 = -INFINITY;
                }
                float o0 = fmaf(ac0[m], dv[m], bb0);
                float o1 = fmaf(ac1[m], dv[m], bb1);
                float o2 = fmaf(ac2[m], dv[m], bb2);
                float o3 = fmaf(ac3[m], dv[m], bb3);
                ps[0] += o0; ps[1] += o1; ps[2] += o2; ps[3] += o3;
                pq[0] += o0 * o0; pq[1] += o1 * o1; pq[2] += o2 * o2; pq[3] += o3 * o3;
                m0 = fmaxf(m0, o0); m1 = fmaxf(m1, o1);
                m2 = fmaxf(m2, o2); m3 = fmaxf(m3, o3);
            }
        }
    }
    if (cur >= 0) {
        atomicMax(&g_poolu[cur * 128 + lane],      enc_f(m0));
        atomicMax(&g_poolu[cur * 128 + 32 + lane], enc_f(m1));
        atomicMax(&g_poolu[cur * 128 + 64 + lane], enc_f(m2));
        atomicMax(&g_poolu[cur * 128 + 96 + lane], enc_f(m3));
    }
    atomicAdd(&sred[lane], ps[0]);
    atomicAdd(&sred[32 + lane], ps[1]);
    atomicAdd(&sred[64 + lane], ps[2]);
    atomicAdd(&sred[96 + lane], ps[3]);
    atomicAdd(&sred[128 + lane], pq[0]);
    atomicAdd(&sred[160 + lane], pq[1]);
    atomicAdd(&sred[192 + lane], pq[2]);
    atomicAdd(&sred[224 + lane], pq[3]);
    __syncthreads();
    if (tid < 256) atomicAdd(&g_stats[192 + tid], sred[tid]);
}

// --------------------------------- final MLP ----------------------------------
__global__ void fc1_kernel(const float* __restrict__ Wf1, const float* __restrict__ bf1,
                           const float* __restrict__ g3, const float* __restrict__ be3,
                           float invn) {
    __shared__ float pr[128];
    int g = blockIdx.x, t = threadIdx.x;
    {
        float mm = g_stats[192 + t] * invn;
        float var = g_stats[320 + t] * invn - mm * mm;
        float s = g3[t] * rsqrtf(var + 1e-5f);
        float sh = fmaf(-mm, s, be3[t]);
        float raw = dec_f(g_poolu[g * 128 + t]);
        pr[t] = fmaxf(fmaf(s, raw, sh), 0.f);
    }
    __syncthreads();
    float acc = bf1[t];
#pragma unroll 8
    for (int k = 0; k < 128; k++) acc = fmaf(pr[k], Wf1[k * 128 + t], acc);
    g_q[g * 128 + t] = acc;
    atomicAdd(&g_stats[448 + t], acc);
    atomicAdd(&g_stats[576 + t], acc * acc);
}

__global__ void fc2_kernel(const float* __restrict__ Wf2, const float* __restrict__ bf2,
                           const float* __restrict__ g4, const float* __restrict__ be4,
                           float* __restrict__ out) {
    __shared__ float r[128];
    __shared__ float red[64];
    int g = blockIdx.x, t = threadIdx.x;  // 64 threads
    const float invg = 1.0f / (float)NGRAPH;
#pragma unroll
    for (int h = 0; h < 2; h++) {
        int c = t + 64 * h;
        float mm = g_stats[448 + c] * invg;
        float var = g_stats[576 + c] * invg - mm * mm;
        float s = g4[c] * rsqrtf(var + 1e-5f);
        float sh = fmaf(-mm, s, be4[c]);
        r[c] = fmaxf(fmaf(s, g_q[g * 128 + c], sh), 0.f);
    }
    __syncthreads();
    float acc = bf2[t];
#pragma unroll 8
    for (int k = 0; k < 128; k++) acc = fmaf(r[k], Wf2[k * 64 + t], acc);
    red[t] = acc * acc;
    for (int off = 32; off > 0; off >>= 1) {
        __syncthreads();
        if (t < off) red[t] += red[t + off];
    }
    __syncthreads();
    float denom = fmaxf(sqrtf(red[0]), 1e-12f);
    out[g * 64 + t] = acc / denom;
}

// --------------------------------- launcher -----------------------------------
extern "C" void kernel_launch(void* const* d_in, const int* in_sizes, int n_in,
                              void* d_out, int out_size) {
    const float* x    = (const float*)d_in[0];
    const int* src    = (const int*)d_in[1];
    const int* dst    = (const int*)d_in[2];
    const int* batch  = (const int*)d_in[3];
    const float* W1  = (const float*)d_in[4];
    const float* b1  = (const float*)d_in[5];
    const float* G1  = (const float*)d_in[6];
    const float* be1 = (const float*)d_in[7];
    const float* W2  = (const float*)d_in[8];
    const float* b2  = (const float*)d_in[9];
    const float* G2  = (const float*)d_in[10];
    const float* be2 = (const float*)d_in[11];
    const float* W3  = (const float*)d_in[12];
    const float* b3  = (const float*)d_in[13];
    const float* G3  = (const float*)d_in[14];
    const float* be3 = (const float*)d_in[15];
    const float* Wf1 = (const float*)d_in[16];
    const float* bf1 = (const float*)d_in[17];
    const float* G4  = (const float*)d_in[18];
    const float* be4 = (const float*)d_in[19];
    const float* Wf2 = (const float*)d_in[20];
    const float* bf2 = (const float*)d_in[21];

    int n = in_sizes[0] / 6;
    int e = in_sizes[1];
    int nb = (n + 1023) / 1024;
    float invn = 1.0f / (float)n;

    deg_kernel<<<(e + 255) / 256, 256>>>(dst, e);
    scan_block_kernel<<<nb, 1024>>>(n);
    scan_fin2_kernel<<<nb, 1024>>>(n, nb);
    fill_kernel<<<(e + 255) / 256, 256>>>(src, dst, e);
    y_kernel<<<(n + 255) / 256, 256>>>(x, n);

    int ngroups = (n + 31) / 32;
    int l1blocks = (ngroups + 7) / 8;       // one 32-node group per warp
    int l23blocks = (n + 63) / 64;          // 8-node chunks per warp (two 4-groups)

    layer1_kernel<<<l1blocks, 256>>>(W1, b1, n);
    layer2_kernel<<<l23blocks, 256>>>(W2, b2, G1, be1, invn, n);
    layer3_kernel<<<l23blocks, 256>>>(W3, b3, G2, be2, batch, invn, n);
    fc1_kernel<<<NGRAPH, 128>>>(Wf1, bf1, G3, be3, invn);
    fc2_kernel<<<NGRAPH, 64>>>(Wf2, bf2, G4, be4, (float*)d_out);
}